// round 1
// baseline (speedup 1.0000x reference)
#include <cuda_runtime.h>
#include <math.h>

#define NN 50000
#define NE 800000
#define D 128

// ---------------- scratch (no allocation allowed) ----------------
__device__ float g_delta[NN * D];
__device__ float g_ds[NN * D];
__device__ float g_q[NN * D];
__device__ float g_k[NN * D];
__device__ float g_v[NN * D];
__device__ float g_agg[NN * D];
__device__ int   g_hist[NN];
__device__ int   g_off[NN + 1];
__device__ int   g_cur[NN];
__device__ int   g_sdst[NE];
__device__ float g_sw[NE];

// ---------------- LayerNorm + exact GELU (warp per row) ----------------
__device__ __forceinline__ float gelu_exact(float h) {
    return 0.5f * h * (1.0f + erff(h * 0.70710678118654752f));
}

__global__ void ln_gelu_kernel(const float* __restrict__ x,
                               const float* __restrict__ sc,
                               const float* __restrict__ bi, int n) {
    int warp = threadIdx.x >> 5;
    int lane = threadIdx.x & 31;
    int row = blockIdx.x * 8 + warp;
    if (row >= n) return;
    float4 v = *(const float4*)(x + row * D + lane * 4);
    float s  = v.x + v.y + v.z + v.w;
    float ss = v.x * v.x + v.y * v.y + v.z * v.z + v.w * v.w;
#pragma unroll
    for (int d = 16; d; d >>= 1) {
        s  += __shfl_xor_sync(0xffffffffu, s, d);
        ss += __shfl_xor_sync(0xffffffffu, ss, d);
    }
    float mean = s * (1.0f / D);
    float var  = ss * (1.0f / D) - mean * mean;
    float rstd = rsqrtf(var + 1e-5f);
    float4 scv = *(const float4*)(sc + lane * 4);
    float4 biv = *(const float4*)(bi + lane * 4);
    float4 o;
    o.x = gelu_exact((v.x - mean) * rstd * scv.x + biv.x);
    o.y = gelu_exact((v.y - mean) * rstd * scv.y + biv.y);
    o.z = gelu_exact((v.z - mean) * rstd * scv.z + biv.z);
    o.w = gelu_exact((v.w - mean) * rstd * scv.w + biv.w);
    *(float4*)(g_delta + row * D + lane * 4) = o;
}

// ---------------- GEMM: C[m,n] = alpha*(sum_k A[m,k]*W[n,k] + bias[n]) + addend[m,n] ----------------
// Block tile 64xD, full K=128 in smem (A transposed, W transposed). 256 threads, 4x8 per thread.
__global__ void __launch_bounds__(256) gemm_kernel(const float* __restrict__ A,
                                                   const float* __restrict__ W,
                                                   const float* __restrict__ bias,
                                                   const float* __restrict__ addend,
                                                   float* __restrict__ C,
                                                   int M, float alpha) {
    extern __shared__ float smem[];
    float* sA = smem;            // [128][64]  k-major
    float* sW = smem + 128 * 64; // [128][128] k-major
    int tid = threadIdx.x;
    int m0 = blockIdx.x * 64;

    // load W (128x128), transpose to k-major
    for (int i4 = tid; i4 < 128 * 32; i4 += 256) {
        int n = i4 >> 5;
        int kc = (i4 & 31) << 2;
        float4 v = *(const float4*)(W + n * D + kc);
        sW[(kc + 0) * 128 + n] = v.x;
        sW[(kc + 1) * 128 + n] = v.y;
        sW[(kc + 2) * 128 + n] = v.z;
        sW[(kc + 3) * 128 + n] = v.w;
    }
    // load A tile (64x128), transpose to k-major
    for (int i4 = tid; i4 < 64 * 32; i4 += 256) {
        int r = i4 >> 5;
        int kc = (i4 & 31) << 2;
        int m = m0 + r;
        float4 v = make_float4(0.f, 0.f, 0.f, 0.f);
        if (m < M) v = *(const float4*)(A + m * D + kc);
        sA[(kc + 0) * 64 + r] = v.x;
        sA[(kc + 1) * 64 + r] = v.y;
        sA[(kc + 2) * 64 + r] = v.z;
        sA[(kc + 3) * 64 + r] = v.w;
    }
    __syncthreads();

    int tx = tid & 15, ty = tid >> 4;
    int n0 = tx * 8, r0 = ty * 4;
    float acc[4][8];
#pragma unroll
    for (int r = 0; r < 4; r++)
#pragma unroll
        for (int c = 0; c < 8; c++) acc[r][c] = 0.f;

#pragma unroll 8
    for (int k = 0; k < 128; k++) {
        float4 a  = *(float4*)&sA[k * 64 + r0];
        float4 b0 = *(float4*)&sW[k * 128 + n0];
        float4 b1 = *(float4*)&sW[k * 128 + n0 + 4];
        float av[4] = {a.x, a.y, a.z, a.w};
        float bv[8] = {b0.x, b0.y, b0.z, b0.w, b1.x, b1.y, b1.z, b1.w};
#pragma unroll
        for (int r = 0; r < 4; r++)
#pragma unroll
            for (int c = 0; c < 8; c++) acc[r][c] += av[r] * bv[c];
    }

    float bvv[8];
#pragma unroll
    for (int c = 0; c < 8; c++) bvv[c] = bias ? bias[n0 + c] : 0.f;

#pragma unroll
    for (int r = 0; r < 4; r++) {
        int m = m0 + r0 + r;
        if (m < M) {
            float o[8];
#pragma unroll
            for (int c = 0; c < 8; c++) {
                o[c] = alpha * (acc[r][c] + bvv[c]);
                if (addend) o[c] += addend[m * D + n0 + c];
            }
            *(float4*)(C + m * D + n0)     = make_float4(o[0], o[1], o[2], o[3]);
            *(float4*)(C + m * D + n0 + 4) = make_float4(o[4], o[5], o[6], o[7]);
        }
    }
}

// ---------------- counting sort of edges by src ----------------
__global__ void hist_kernel(const int* __restrict__ src, int E) {
    int e = blockIdx.x * blockDim.x + threadIdx.x;
    if (e < E) atomicAdd(&g_hist[src[e]], 1);
}

__global__ void scan_kernel(int n) {
    __shared__ int warp_sums[32];
    int t = threadIdx.x;  // 1024 threads
    int lane = t & 31, wid = t >> 5;
    int carry = 0;
    for (int base = 0; base < n; base += 1024) {
        int i = base + t;
        int v = (i < n) ? g_hist[i] : 0;
        int x = v;
#pragma unroll
        for (int d = 1; d < 32; d <<= 1) {
            int nb = __shfl_up_sync(0xffffffffu, x, d);
            if (lane >= d) x += nb;
        }
        if (lane == 31) warp_sums[wid] = x;
        __syncthreads();
        if (wid == 0) {
            int sv = warp_sums[lane];
#pragma unroll
            for (int d = 1; d < 32; d <<= 1) {
                int nb = __shfl_up_sync(0xffffffffu, sv, d);
                if (lane >= d) sv += nb;
            }
            warp_sums[lane] = sv;
        }
        __syncthreads();
        int warp_off = (wid == 0) ? 0 : warp_sums[wid - 1];
        int excl = carry + warp_off + x - v;
        if (i < n) {
            g_off[i] = excl;
            g_cur[i] = excl;
        }
        carry += warp_sums[31];
        __syncthreads();
    }
    if (t == 0) g_off[n] = carry;
}

__global__ void scatter_kernel(const int* __restrict__ src, const int* __restrict__ dst,
                               const float* __restrict__ w, int E) {
    int e = blockIdx.x * blockDim.x + threadIdx.x;
    if (e < E) {
        int s = src[e];
        int p = atomicAdd(&g_cur[s], 1);
        g_sdst[p] = dst[e];
        g_sw[p]   = w[e];
    }
}

// ---------------- aggregation: warp per src node, no atomics ----------------
__global__ void agg_kernel(int n) {
    int warp = (blockIdx.x * blockDim.x + threadIdx.x) >> 5;
    int lane = threadIdx.x & 31;
    if (warp >= n) return;
    int beg = g_off[warp], end = g_off[warp + 1];
    float4 q = *(const float4*)&g_q[warp * D + lane * 4];
    float4 acc = make_float4(0.f, 0.f, 0.f, 0.f);
    for (int e = beg; e < end; e++) {
        int dst  = g_sdst[e];
        float wgt = g_sw[e];
        const float4 kv = *(const float4*)&g_k[dst * D + lane * 4];
        float p = q.x * kv.x + q.y * kv.y + q.z * kv.z + q.w * kv.w;
        p += __shfl_xor_sync(0xffffffffu, p, 1);
        p += __shfl_xor_sync(0xffffffffu, p, 2);  // per-head (16-dim) dot, 4 lanes/head
        float attn = wgt / (1.0f + expf(-p));
        const float4 vv = *(const float4*)&g_v[dst * D + lane * 4];
        acc.x += attn * vv.x;
        acc.y += attn * vv.y;
        acc.z += attn * vv.z;
        acc.w += attn * vv.w;
    }
    *(float4*)&g_agg[warp * D + lane * 4] = acc;
}

// ---------------- launch ----------------
extern "C" void kernel_launch(void* const* d_in, const int* in_sizes, int n_in,
                              void* d_out, int out_size) {
    const float* in_feats = (const float*)d_in[0];
    const float* struc    = (const float*)d_in[1];
    const float* ew       = (const float*)d_in[2];
    const float* ln_s     = (const float*)d_in[3];
    const float* ln_b     = (const float*)d_in[4];
    const float* Ws = (const float*)d_in[5];
    const float* bs = (const float*)d_in[6];
    const float* Wq = (const float*)d_in[7];
    const float* bq = (const float*)d_in[8];
    const float* Wk = (const float*)d_in[9];
    const float* bk = (const float*)d_in[10];
    const float* Wv = (const float*)d_in[11];
    const float* bv = (const float*)d_in[12];
    const float* Wo = (const float*)d_in[13];
    const int* eids = (const int*)d_in[14];

    int E = in_sizes[2];
    int N = in_sizes[0] / D;
    const int* src = eids;
    const int* dst = eids + E;

    cudaFuncSetAttribute((const void*)gemm_kernel,
                         cudaFuncAttributeMaxDynamicSharedMemorySize, 98304);

    float *p_delta, *p_ds, *p_q, *p_k, *p_v, *p_agg;
    int* p_hist;
    cudaGetSymbolAddress((void**)&p_delta, g_delta);
    cudaGetSymbolAddress((void**)&p_ds, g_ds);
    cudaGetSymbolAddress((void**)&p_q, g_q);
    cudaGetSymbolAddress((void**)&p_k, g_k);
    cudaGetSymbolAddress((void**)&p_v, g_v);
    cudaGetSymbolAddress((void**)&p_agg, g_agg);
    cudaGetSymbolAddress((void**)&p_hist, g_hist);

    const size_t smem = 98304;
    int gblocks = (N + 63) / 64;

    ln_gelu_kernel<<<(N + 7) / 8, 256>>>(in_feats, ln_s, ln_b, N);
    // delta_struc = delta + struc @ Ws^T + bs
    gemm_kernel<<<gblocks, 256, smem>>>(struc, Ws, bs, p_delta, p_ds, N, 1.0f);
    // q = (delta_struc @ Wq^T + bq) / sqrt(16)
    gemm_kernel<<<gblocks, 256, smem>>>(p_ds, Wq, bq, nullptr, p_q, N, 0.25f);
    // k = delta_struc @ Wk^T + bk
    gemm_kernel<<<gblocks, 256, smem>>>(p_ds, Wk, bk, nullptr, p_k, N, 1.0f);
    // v = delta @ Wv^T + bv
    gemm_kernel<<<gblocks, 256, smem>>>(p_delta, Wv, bv, nullptr, p_v, N, 1.0f);

    // counting sort edges by src
    cudaMemsetAsync(p_hist, 0, N * sizeof(int));
    hist_kernel<<<(E + 255) / 256, 256>>>(src, E);
    scan_kernel<<<1, 1024>>>(N);
    scatter_kernel<<<(E + 255) / 256, 256>>>(src, dst, ew, E);

    // per-node sigmoid attention aggregation
    agg_kernel<<<(N * 32 + 255) / 256, 256>>>(N);

    // out = agg @ Wo^T + in_feats
    gemm_kernel<<<gblocks, 256, smem>>>(p_agg, Wo, nullptr, in_feats, (float*)d_out, N, 1.0f);
}

// round 2
// speedup vs baseline: 1.9170x; 1.9170x over previous
#include <cuda_runtime.h>
#include <math.h>

#define NN 50000
#define NE 800000
#define D 128

// ---------------- scratch (no allocation allowed) ----------------
__device__ float g_delta[NN * D];
__device__ float g_ds[NN * D];
__device__ float g_q[NN * D];
__device__ float g_k[NN * D];
__device__ float g_v[NN * D];
__device__ float g_agg[NN * D];
__device__ int   g_hist[NN];
__device__ int   g_off[NN + 1];
__device__ int   g_cur[NN];
__device__ int   g_sdst[NE];
__device__ float g_sw[NE];

// ---------------- f32x2 packed helpers (Blackwell FFMA2) ----------------
typedef unsigned long long u64;

__device__ __forceinline__ u64 pack2(float lo, float hi) {
    u64 r;
    asm("mov.b64 %0, {%1, %2};" : "=l"(r) : "f"(lo), "f"(hi));
    return r;
}
__device__ __forceinline__ void unpack2(u64 v, float& lo, float& hi) {
    asm("mov.b64 {%0, %1}, %2;" : "=f"(lo), "=f"(hi) : "l"(v));
}
__device__ __forceinline__ void fma2(u64& d, u64 a, u64 b) {
    asm("fma.rn.f32x2 %0, %1, %2, %0;" : "+l"(d) : "l"(a), "l"(b));
}

// ---------------- LayerNorm + exact GELU (warp per row) ----------------
__device__ __forceinline__ float gelu_exact(float h) {
    return 0.5f * h * (1.0f + erff(h * 0.70710678118654752f));
}

__global__ void ln_gelu_kernel(const float* __restrict__ x,
                               const float* __restrict__ sc,
                               const float* __restrict__ bi, int n) {
    int warp = threadIdx.x >> 5;
    int lane = threadIdx.x & 31;
    int row = blockIdx.x * 8 + warp;
    if (row >= n) return;
    float4 v = *(const float4*)(x + row * D + lane * 4);
    float s  = v.x + v.y + v.z + v.w;
    float ss = v.x * v.x + v.y * v.y + v.z * v.z + v.w * v.w;
#pragma unroll
    for (int d = 16; d; d >>= 1) {
        s  += __shfl_xor_sync(0xffffffffu, s, d);
        ss += __shfl_xor_sync(0xffffffffu, ss, d);
    }
    float mean = s * (1.0f / D);
    float var  = ss * (1.0f / D) - mean * mean;
    float rstd = rsqrtf(var + 1e-5f);
    float4 scv = *(const float4*)(sc + lane * 4);
    float4 biv = *(const float4*)(bi + lane * 4);
    float4 o;
    o.x = gelu_exact((v.x - mean) * rstd * scv.x + biv.x);
    o.y = gelu_exact((v.y - mean) * rstd * scv.y + biv.y);
    o.z = gelu_exact((v.z - mean) * rstd * scv.z + biv.z);
    o.w = gelu_exact((v.w - mean) * rstd * scv.w + biv.w);
    *(float4*)(g_delta + row * D + lane * 4) = o;
}

// ---------------- GEMM: C[m,n] = alpha*(sum_k A[m,k]*W[n,k] + bias[n]) + addend[m,n]
// Block tile 64(m) x 128(n), full K=128 resident. 256 threads = 8 warps.
// Warp w: m rows [w*8, w*8+8); lane: n columns [lane*4, lane*4+4).
// sA: m-major [64][128] (direct copy, broadcast reads).
// sW: k-major [128][128] (conflict-free stores via lane-spans-n transpose loader,
//                         conflict-free LDS.128 reads at 16B lane stride).
// Inner product via packed fma.rn.f32x2 (2 fp32 FMA per op).
__global__ void __launch_bounds__(256) gemm_kernel(const float* __restrict__ A,
                                                   const float* __restrict__ W,
                                                   const float* __restrict__ bias,
                                                   const float* __restrict__ addend,
                                                   float* __restrict__ C,
                                                   int M, float alpha) {
    extern __shared__ float smem[];
    float* sA = smem;             // [64][128]  m-major
    float* sW = smem + 64 * 128;  // [128][128] k-major
    int tid = threadIdx.x;
    int m0 = blockIdx.x * 64;

    // Load W (n-major [128][128] in gmem) transposed into k-major sW.
    // Lanes span n => smem stores are stride-1 across lanes (conflict-free).
    for (int idx = tid; idx < 128 * 32; idx += 256) {
        int n  = idx & 127;
        int k4 = idx >> 7;          // 0..31, 4 k per thread
        float4 v = *(const float4*)(W + n * D + k4 * 4);
        sW[(k4 * 4 + 0) * 128 + n] = v.x;
        sW[(k4 * 4 + 1) * 128 + n] = v.y;
        sW[(k4 * 4 + 2) * 128 + n] = v.z;
        sW[(k4 * 4 + 3) * 128 + n] = v.w;
    }
    // Load A tile (64x128) straight (coalesced, conflict-free).
    for (int idx = tid; idx < 64 * 32; idx += 256) {
        int r  = idx >> 5;
        int c4 = (idx & 31) << 2;
        int m = m0 + r;
        float4 v = make_float4(0.f, 0.f, 0.f, 0.f);
        if (m < M) v = *(const float4*)(A + m * D + c4);
        *(float4*)&sA[r * 128 + c4] = v;
    }
    __syncthreads();

    int w = tid >> 5;
    int lane = tid & 31;
    int n0 = lane * 4;
    const float* sArow = sA + (w * 8) * 128;

    u64 acc[8][2];
#pragma unroll
    for (int r = 0; r < 8; r++) { acc[r][0] = 0ull; acc[r][1] = 0ull; }

#pragma unroll 4
    for (int k0 = 0; k0 < 128; k0 += 4) {
        // stage b: 4 rows of sW, each a conflict-free LDS.128; float4 => 2 n-pairs free
        u64 b2[4][2];
#pragma unroll
        for (int kk = 0; kk < 4; kk++) {
            float4 b = *(const float4*)&sW[(k0 + kk) * 128 + n0];
            b2[kk][0] = pack2(b.x, b.y);
            b2[kk][1] = pack2(b.z, b.w);
        }
#pragma unroll
        for (int r = 0; r < 8; r++) {
            float4 a = *(const float4*)&sArow[r * 128 + k0];   // 16B broadcast
            u64 a0 = pack2(a.x, a.x);
            u64 a1 = pack2(a.y, a.y);
            u64 a2 = pack2(a.z, a.z);
            u64 a3 = pack2(a.w, a.w);
            fma2(acc[r][0], a0, b2[0][0]);  fma2(acc[r][1], a0, b2[0][1]);
            fma2(acc[r][0], a1, b2[1][0]);  fma2(acc[r][1], a1, b2[1][1]);
            fma2(acc[r][0], a2, b2[2][0]);  fma2(acc[r][1], a2, b2[2][1]);
            fma2(acc[r][0], a3, b2[3][0]);  fma2(acc[r][1], a3, b2[3][1]);
        }
    }

    float b0 = bias ? bias[n0]     : 0.f;
    float b1 = bias ? bias[n0 + 1] : 0.f;
    float b2v = bias ? bias[n0 + 2] : 0.f;
    float b3 = bias ? bias[n0 + 3] : 0.f;

#pragma unroll
    for (int r = 0; r < 8; r++) {
        int m = m0 + w * 8 + r;
        if (m < M) {
            float o0, o1, o2, o3;
            unpack2(acc[r][0], o0, o1);
            unpack2(acc[r][1], o2, o3);
            o0 = alpha * (o0 + b0);
            o1 = alpha * (o1 + b1);
            o2 = alpha * (o2 + b2v);
            o3 = alpha * (o3 + b3);
            if (addend) {
                float4 ad = *(const float4*)(addend + m * D + n0);
                o0 += ad.x; o1 += ad.y; o2 += ad.z; o3 += ad.w;
            }
            *(float4*)(C + m * D + n0) = make_float4(o0, o1, o2, o3);
        }
    }
}

// ---------------- counting sort of edges by src ----------------
__global__ void hist_kernel(const int* __restrict__ src, int E) {
    int e = blockIdx.x * blockDim.x + threadIdx.x;
    if (e < E) atomicAdd(&g_hist[src[e]], 1);
}

__global__ void scan_kernel(int n) {
    __shared__ int warp_sums[32];
    int t = threadIdx.x;  // 1024 threads
    int lane = t & 31, wid = t >> 5;
    int carry = 0;
    for (int base = 0; base < n; base += 1024) {
        int i = base + t;
        int v = (i < n) ? g_hist[i] : 0;
        int x = v;
#pragma unroll
        for (int d = 1; d < 32; d <<= 1) {
            int nb = __shfl_up_sync(0xffffffffu, x, d);
            if (lane >= d) x += nb;
        }
        if (lane == 31) warp_sums[wid] = x;
        __syncthreads();
        if (wid == 0) {
            int sv = warp_sums[lane];
#pragma unroll
            for (int d = 1; d < 32; d <<= 1) {
                int nb = __shfl_up_sync(0xffffffffu, sv, d);
                if (lane >= d) sv += nb;
            }
            warp_sums[lane] = sv;
        }
        __syncthreads();
        int warp_off = (wid == 0) ? 0 : warp_sums[wid - 1];
        int excl = carry + warp_off + x - v;
        if (i < n) {
            g_off[i] = excl;
            g_cur[i] = excl;
        }
        carry += warp_sums[31];
        __syncthreads();
    }
    if (t == 0) g_off[n] = carry;
}

__global__ void scatter_kernel(const int* __restrict__ src, const int* __restrict__ dst,
                               const float* __restrict__ w, int E) {
    int e = blockIdx.x * blockDim.x + threadIdx.x;
    if (e < E) {
        int s = src[e];
        int p = atomicAdd(&g_cur[s], 1);
        g_sdst[p] = dst[e];
        g_sw[p]   = w[e];
    }
}

// ---------------- aggregation: warp per src node, no atomics ----------------
__global__ void agg_kernel(int n) {
    int warp = (blockIdx.x * blockDim.x + threadIdx.x) >> 5;
    int lane = threadIdx.x & 31;
    if (warp >= n) return;
    int beg = g_off[warp], end = g_off[warp + 1];
    float4 q = *(const float4*)&g_q[warp * D + lane * 4];
    float4 acc = make_float4(0.f, 0.f, 0.f, 0.f);
    for (int e = beg; e < end; e++) {
        int dst  = g_sdst[e];
        float wgt = g_sw[e];
        const float4 kv = *(const float4*)&g_k[dst * D + lane * 4];
        float p = q.x * kv.x + q.y * kv.y + q.z * kv.z + q.w * kv.w;
        p += __shfl_xor_sync(0xffffffffu, p, 1);
        p += __shfl_xor_sync(0xffffffffu, p, 2);  // per-head (16-dim) dot, 4 lanes/head
        float attn = wgt / (1.0f + expf(-p));
        const float4 vv = *(const float4*)&g_v[dst * D + lane * 4];
        acc.x += attn * vv.x;
        acc.y += attn * vv.y;
        acc.z += attn * vv.z;
        acc.w += attn * vv.w;
    }
    *(float4*)&g_agg[warp * D + lane * 4] = acc;
}

// ---------------- launch ----------------
extern "C" void kernel_launch(void* const* d_in, const int* in_sizes, int n_in,
                              void* d_out, int out_size) {
    const float* in_feats = (const float*)d_in[0];
    const float* struc    = (const float*)d_in[1];
    const float* ew       = (const float*)d_in[2];
    const float* ln_s     = (const float*)d_in[3];
    const float* ln_b     = (const float*)d_in[4];
    const float* Ws = (const float*)d_in[5];
    const float* bs = (const float*)d_in[6];
    const float* Wq = (const float*)d_in[7];
    const float* bq = (const float*)d_in[8];
    const float* Wk = (const float*)d_in[9];
    const float* bk = (const float*)d_in[10];
    const float* Wv = (const float*)d_in[11];
    const float* bv = (const float*)d_in[12];
    const float* Wo = (const float*)d_in[13];
    const int* eids = (const int*)d_in[14];

    int E = in_sizes[2];
    int N = in_sizes[0] / D;
    const int* src = eids;
    const int* dst = eids + E;

    cudaFuncSetAttribute((const void*)gemm_kernel,
                         cudaFuncAttributeMaxDynamicSharedMemorySize, 98304);

    float *p_delta, *p_ds, *p_q, *p_k, *p_v, *p_agg;
    int* p_hist;
    cudaGetSymbolAddress((void**)&p_delta, g_delta);
    cudaGetSymbolAddress((void**)&p_ds, g_ds);
    cudaGetSymbolAddress((void**)&p_q, g_q);
    cudaGetSymbolAddress((void**)&p_k, g_k);
    cudaGetSymbolAddress((void**)&p_v, g_v);
    cudaGetSymbolAddress((void**)&p_agg, g_agg);
    cudaGetSymbolAddress((void**)&p_hist, g_hist);

    const size_t smem = 98304;
    int gblocks = (N + 63) / 64;

    ln_gelu_kernel<<<(N + 7) / 8, 256>>>(in_feats, ln_s, ln_b, N);
    // delta_struc = delta + struc @ Ws^T + bs
    gemm_kernel<<<gblocks, 256, smem>>>(struc, Ws, bs, p_delta, p_ds, N, 1.0f);
    // q = (delta_struc @ Wq^T + bq) / sqrt(16)
    gemm_kernel<<<gblocks, 256, smem>>>(p_ds, Wq, bq, nullptr, p_q, N, 0.25f);
    // k = delta_struc @ Wk^T + bk
    gemm_kernel<<<gblocks, 256, smem>>>(p_ds, Wk, bk, nullptr, p_k, N, 1.0f);
    // v = delta @ Wv^T + bv
    gemm_kernel<<<gblocks, 256, smem>>>(p_delta, Wv, bv, nullptr, p_v, N, 1.0f);

    // counting sort edges by src
    cudaMemsetAsync(p_hist, 0, N * sizeof(int));
    hist_kernel<<<(E + 255) / 256, 256>>>(src, E);
    scan_kernel<<<1, 1024>>>(N);
    scatter_kernel<<<(E + 255) / 256, 256>>>(src, dst, ew, E);

    // per-node sigmoid attention aggregation
    agg_kernel<<<(N * 32 + 255) / 256, 256>>>(N);

    // out = agg @ Wo^T + in_feats
    gemm_kernel<<<gblocks, 256, smem>>>(p_agg, Wo, nullptr, in_feats, (float*)d_out, N, 1.0f);
}

// round 4
// speedup vs baseline: 2.5487x; 1.3295x over previous
#include <cuda_runtime.h>
#include <cuda_bf16.h>
#include <math.h>
#include <stdint.h>

#define NN 50000
#define NE 800000
#define D 128
#define NTILES_MAX 391
#define NP (NTILES_MAX * 128)
#define PITCH 136                      // bf16 elems per smem row (conflict-free ldmatrix)
#define SMEM_SZ (4 * 128 * PITCH * 2)  // 4 tiles: Ah, Al, Wh, Wl

// ---------------- scratch (no allocation allowed) ----------------
__device__ float g_delta[NP * D];
__device__ float g_q[NP * D];
__device__ float g_k[NP * D];
__device__ float g_v[NP * D];
// bf16 hi/lo operand tiles, row-major [NP][D]
__device__ __nv_bfloat16 g_sh[NP * D], g_sl[NP * D];     // struc
__device__ __nv_bfloat16 g_dh[NP * D], g_dl[NP * D];     // delta
__device__ __nv_bfloat16 g_dsh[NP * D], g_dsl[NP * D];   // delta_struc
__device__ __nv_bfloat16 g_agh[NP * D], g_agl[NP * D];   // agg (pads stay zero-init)
__device__ __nv_bfloat16 g_wh[5 * D * D], g_wl[5 * D * D];
__device__ int   g_hist[NN];
__device__ int   g_off[NN + 1];
__device__ int   g_cur[NN];
__device__ int   g_sdst[NE];
__device__ float g_sw[NE];

// ---------------- helpers ----------------
__device__ __forceinline__ uint32_t smem_u32(const void* p) {
    uint32_t a;
    asm("{ .reg .u64 t; cvta.to.shared.u64 t, %1; cvt.u32.u64 %0, t; }" : "=r"(a) : "l"(p));
    return a;
}

#define LDM_X4(r0, r1, r2, r3, addr) \
    asm volatile("ldmatrix.sync.aligned.m8n8.x4.shared.b16 {%0,%1,%2,%3}, [%4];" \
                 : "=r"(r0), "=r"(r1), "=r"(r2), "=r"(r3) : "r"(addr))

#define MMA16816(d, a, b) \
    asm volatile("mma.sync.aligned.m16n8k16.row.col.f32.bf16.bf16.f32 " \
                 "{%0,%1,%2,%3}, {%4,%5,%6,%7}, {%8,%9}, {%0,%1,%2,%3};" \
                 : "+f"((d)[0]), "+f"((d)[1]), "+f"((d)[2]), "+f"((d)[3]) \
                 : "r"((a)[0]), "r"((a)[1]), "r"((a)[2]), "r"((a)[3]), \
                   "r"((b)[0]), "r"((b)[1]))

// split f32 pair -> bf16 hi/lo, store row-major at even col c
__device__ __forceinline__ void store_hl(__nv_bfloat16* bh, __nv_bfloat16* bl,
                                         size_t idx, float x, float y) {
    __nv_bfloat16 hx = __float2bfloat16(x), hy = __float2bfloat16(y);
    float lx = x - __bfloat162float(hx), ly = y - __bfloat162float(hy);
    __nv_bfloat162 hv, lv;
    hv.x = hx; hv.y = hy;
    lv.x = __float2bfloat16(lx); lv.y = __float2bfloat16(ly);
    *(__nv_bfloat162*)(bh + idx) = hv;
    *(__nv_bfloat162*)(bl + idx) = lv;
}

// ---------------- LayerNorm + exact GELU + hi/lo emit (warp per row) ----------------
__device__ __forceinline__ float gelu_exact(float h) {
    return 0.5f * h * (1.0f + erff(h * 0.70710678118654752f));
}

__global__ void ln_gelu_kernel(const float* __restrict__ x,
                               const float* __restrict__ struc,
                               const float* __restrict__ sc,
                               const float* __restrict__ bi, int n, int npad) {
    int warp = threadIdx.x >> 5;
    int lane = threadIdx.x & 31;
    int row = blockIdx.x * 8 + warp;
    if (row >= npad) return;
    int c0 = lane * 4;
    size_t base = (size_t)row * D + c0;

    float4 o = make_float4(0.f, 0.f, 0.f, 0.f);
    float4 sv = make_float4(0.f, 0.f, 0.f, 0.f);
    if (row < n) {
        float4 v = *(const float4*)(x + base);
        sv = *(const float4*)(struc + base);
        float s  = v.x + v.y + v.z + v.w;
        float ss = v.x * v.x + v.y * v.y + v.z * v.z + v.w * v.w;
#pragma unroll
        for (int d = 16; d; d >>= 1) {
            s  += __shfl_xor_sync(0xffffffffu, s, d);
            ss += __shfl_xor_sync(0xffffffffu, ss, d);
        }
        float mean = s * (1.0f / D);
        float var  = ss * (1.0f / D) - mean * mean;
        float rstd = rsqrtf(var + 1e-5f);
        float4 scv = *(const float4*)(sc + c0);
        float4 biv = *(const float4*)(bi + c0);
        o.x = gelu_exact((v.x - mean) * rstd * scv.x + biv.x);
        o.y = gelu_exact((v.y - mean) * rstd * scv.y + biv.y);
        o.z = gelu_exact((v.z - mean) * rstd * scv.z + biv.z);
        o.w = gelu_exact((v.w - mean) * rstd * scv.w + biv.w);
    }
    *(float4*)(g_delta + base) = o;     // f32 delta (addend for GEMM1), zeros on pad
    store_hl(g_dh, g_dl, base,     o.x, o.y);
    store_hl(g_dh, g_dl, base + 2, o.z, o.w);
    store_hl(g_sh, g_sl, base,     sv.x, sv.y);
    store_hl(g_sh, g_sl, base + 2, sv.z, sv.w);
}

// ---------------- weight split (5 x 128x128) ----------------
__global__ void conv_w_kernel(const float* __restrict__ W0, const float* __restrict__ W1,
                              const float* __restrict__ W2, const float* __restrict__ W3,
                              const float* __restrict__ W4) {
    int widx = blockIdx.x;
    const float* W = widx == 0 ? W0 : widx == 1 ? W1 : widx == 2 ? W2 : widx == 3 ? W3 : W4;
    __nv_bfloat16* bh = g_wh + (size_t)widx * D * D;
    __nv_bfloat16* bl = g_wl + (size_t)widx * D * D;
    for (int p = threadIdx.x; p < D * D / 2; p += blockDim.x) {
        size_t i = (size_t)p * 2;
        store_hl(bh, bl, i, W[i], W[i + 1]);
    }
}

// ---------------- mma.sync GEMM: CTA = 128m x 128n x 128k, 3-term bf16 split ----------------
// out[m,n] = alpha*(sum_k A[m,k]*W[n,k] + bias[n]) + addend[m,n]
__global__ void __launch_bounds__(256, 1) mma_gemm(
    const __nv_bfloat16* __restrict__ Ah, const __nv_bfloat16* __restrict__ Al,
    int widx, const float* __restrict__ bias, const float* __restrict__ addend,
    float* __restrict__ outF, __nv_bfloat16* __restrict__ outH, __nv_bfloat16* __restrict__ outL,
    int Mreal, float alpha)
{
    extern __shared__ char smem_raw[];
    __nv_bfloat16* sAh = (__nv_bfloat16*)smem_raw;
    __nv_bfloat16* sAl = sAh + 128 * PITCH;
    __nv_bfloat16* sWh = sAl + 128 * PITCH;
    __nv_bfloat16* sWl = sWh + 128 * PITCH;
    int tid = threadIdx.x, wid = tid >> 5, lane = tid & 31;
    size_t tile = blockIdx.x;

    // load 4 tiles gmem (row-major 128x128 bf16) -> smem (pitch 136)
    {
        const float4* gAh = (const float4*)(Ah + tile * 128 * D);
        const float4* gAl = (const float4*)(Al + tile * 128 * D);
        const float4* gWh = (const float4*)(g_wh + (size_t)widx * D * D);
        const float4* gWl = (const float4*)(g_wl + (size_t)widx * D * D);
        for (int idx = tid; idx < 128 * 16; idx += 256) {
            int r = idx >> 4, c8 = (idx & 15) * 8;
            *(float4*)(sAh + r * PITCH + c8) = gAh[idx];
            *(float4*)(sAl + r * PITCH + c8) = gAl[idx];
            *(float4*)(sWh + r * PITCH + c8) = gWh[idx];
            *(float4*)(sWl + r * PITCH + c8) = gWl[idx];
        }
    }
    __syncthreads();

    int m0 = (wid & 3) * 32;          // warp m-block
    int n0w = (wid >> 2) * 64;        // warp n-block

    // ldmatrix per-lane addresses
    int aRow = ((lane >> 3) & 1) * 8 + (lane & 7);
    int aCol = (lane >> 4) * 8;
    uint32_t aOffH = smem_u32(sAh) + ((m0 + aRow) * PITCH + aCol) * 2;
    uint32_t aOffL = smem_u32(sAl) + ((m0 + aRow) * PITCH + aCol) * 2;
    int bRow = (lane >> 4) * 8 + (lane & 7);
    int bCol = ((lane >> 3) & 1) * 8;
    uint32_t bOffH = smem_u32(sWh) + ((n0w + bRow) * PITCH + bCol) * 2;
    uint32_t bOffL = smem_u32(sWl) + ((n0w + bRow) * PITCH + bCol) * 2;
    const uint32_t aStep = 16 * PITCH * 2;   // +16 rows

    float acc[2][8][4];
#pragma unroll
    for (int mi = 0; mi < 2; mi++)
#pragma unroll
        for (int ni = 0; ni < 8; ni++)
#pragma unroll
            for (int j = 0; j < 4; j++) acc[mi][ni][j] = 0.f;

#pragma unroll 1
    for (int s = 0; s < 8; s++) {
        uint32_t ko = s * 32;         // 16 bf16 per k-step
        uint32_t ah[2][4], al[2][4], bh[8][2], bl[8][2];
        LDM_X4(ah[0][0], ah[0][1], ah[0][2], ah[0][3], aOffH + ko);
        LDM_X4(ah[1][0], ah[1][1], ah[1][2], ah[1][3], aOffH + aStep + ko);
        LDM_X4(al[0][0], al[0][1], al[0][2], al[0][3], aOffL + ko);
        LDM_X4(al[1][0], al[1][1], al[1][2], al[1][3], aOffL + aStep + ko);
#pragma unroll
        for (int nb = 0; nb < 4; nb++) {
            uint32_t t0, t1, t2, t3;
            LDM_X4(t0, t1, t2, t3, bOffH + nb * aStep + ko);
            bh[nb * 2][0] = t0; bh[nb * 2][1] = t1;
            bh[nb * 2 + 1][0] = t2; bh[nb * 2 + 1][1] = t3;
            LDM_X4(t0, t1, t2, t3, bOffL + nb * aStep + ko);
            bl[nb * 2][0] = t0; bl[nb * 2][1] = t1;
            bl[nb * 2 + 1][0] = t2; bl[nb * 2 + 1][1] = t3;
        }
#pragma unroll
        for (int mi = 0; mi < 2; mi++)
#pragma unroll
            for (int ni = 0; ni < 8; ni++) {
                MMA16816(acc[mi][ni], ah[mi], bh[ni]);
                MMA16816(acc[mi][ni], ah[mi], bl[ni]);
                MMA16816(acc[mi][ni], al[mi], bh[ni]);
            }
    }

    // epilogue
    int r = lane >> 2, c2 = (lane & 3) * 2;
#pragma unroll
    for (int mi = 0; mi < 2; mi++) {
#pragma unroll
        for (int half = 0; half < 2; half++) {
            int grow = (int)tile * 128 + m0 + mi * 16 + half * 8 + r;
            bool valid = grow < Mreal;
            if (!valid) continue;
#pragma unroll
            for (int ni = 0; ni < 8; ni++) {
                int col = n0w + ni * 8 + c2;
                float o0 = acc[mi][ni][half * 2 + 0];
                float o1 = acc[mi][ni][half * 2 + 1];
                if (bias) { o0 += bias[col]; o1 += bias[col + 1]; }
                o0 *= alpha; o1 *= alpha;
                size_t idx = (size_t)grow * D + col;
                if (addend) {
                    float2 ad = *(const float2*)(addend + idx);
                    o0 += ad.x; o1 += ad.y;
                }
                if (outF) *(float2*)(outF + idx) = make_float2(o0, o1);
                if (outH) store_hl(outH, outL, idx, o0, o1);
            }
        }
    }
}

// ---------------- counting sort of edges by src ----------------
__global__ void hist_kernel(const int* __restrict__ src, int E) {
    int e = blockIdx.x * blockDim.x + threadIdx.x;
    if (e < E) atomicAdd(&g_hist[src[e]], 1);
}

__global__ void scan_kernel(int n) {
    __shared__ int warp_sums[32];
    int t = threadIdx.x;  // 1024 threads
    int lane = t & 31, wid = t >> 5;
    int carry = 0;
    for (int base = 0; base < n; base += 1024) {
        int i = base + t;
        int v = (i < n) ? g_hist[i] : 0;
        int x = v;
#pragma unroll
        for (int d = 1; d < 32; d <<= 1) {
            int nb = __shfl_up_sync(0xffffffffu, x, d);
            if (lane >= d) x += nb;
        }
        if (lane == 31) warp_sums[wid] = x;
        __syncthreads();
        if (wid == 0) {
            int sv = warp_sums[lane];
#pragma unroll
            for (int d = 1; d < 32; d <<= 1) {
                int nb = __shfl_up_sync(0xffffffffu, sv, d);
                if (lane >= d) sv += nb;
            }
            warp_sums[lane] = sv;
        }
        __syncthreads();
        int warp_off = (wid == 0) ? 0 : warp_sums[wid - 1];
        int excl = carry + warp_off + x - v;
        if (i < n) {
            g_off[i] = excl;
            g_cur[i] = excl;
        }
        carry += warp_sums[31];
        __syncthreads();
    }
    if (t == 0) g_off[n] = carry;
}

__global__ void scatter_kernel(const int* __restrict__ src, const int* __restrict__ dst,
                               const float* __restrict__ w, int E) {
    int e = blockIdx.x * blockDim.x + threadIdx.x;
    if (e < E) {
        int s = src[e];
        int p = atomicAdd(&g_cur[s], 1);
        g_sdst[p] = dst[e];
        g_sw[p]   = w[e];
    }
}

// ---------------- aggregation: warp per src node, emits agg hi/lo ----------------
__global__ void agg_kernel(int n) {
    int warp = (blockIdx.x * blockDim.x + threadIdx.x) >> 5;
    int lane = threadIdx.x & 31;
    if (warp >= n) return;
    int beg = g_off[warp], end = g_off[warp + 1];
    float4 q = *(const float4*)&g_q[(size_t)warp * D + lane * 4];
    float4 acc = make_float4(0.f, 0.f, 0.f, 0.f);
    for (int e = beg; e < end; e++) {
        int dst  = g_sdst[e];
        float wgt = g_sw[e];
        const float4 kv = *(const float4*)&g_k[(size_t)dst * D + lane * 4];
        float p = q.x * kv.x + q.y * kv.y + q.z * kv.z + q.w * kv.w;
        p += __shfl_xor_sync(0xffffffffu, p, 1);
        p += __shfl_xor_sync(0xffffffffu, p, 2);  // per-head (16-dim) dot, 4 lanes/head
        float attn = wgt / (1.0f + expf(-p));
        const float4 vv = *(const float4*)&g_v[(size_t)dst * D + lane * 4];
        acc.x += attn * vv.x;
        acc.y += attn * vv.y;
        acc.z += attn * vv.z;
        acc.w += attn * vv.w;
    }
    size_t base = (size_t)warp * D + lane * 4;
    store_hl(g_agh, g_agl, base,     acc.x, acc.y);
    store_hl(g_agh, g_agl, base + 2, acc.z, acc.w);
}

// ---------------- launch ----------------
extern "C" void kernel_launch(void* const* d_in, const int* in_sizes, int n_in,
                              void* d_out, int out_size) {
    const float* in_feats = (const float*)d_in[0];
    const float* struc    = (const float*)d_in[1];
    const float* ew       = (const float*)d_in[2];
    const float* ln_s     = (const float*)d_in[3];
    const float* ln_b     = (const float*)d_in[4];
    const float* Ws = (const float*)d_in[5];
    const float* bs = (const float*)d_in[6];
    const float* Wq = (const float*)d_in[7];
    const float* bq = (const float*)d_in[8];
    const float* Wk = (const float*)d_in[9];
    const float* bk = (const float*)d_in[10];
    const float* Wv = (const float*)d_in[11];
    const float* bv = (const float*)d_in[12];
    const float* Wo = (const float*)d_in[13];
    const int* eids = (const int*)d_in[14];

    int E = in_sizes[2];
    int N = in_sizes[0] / D;
    int tiles = (N + 127) / 128;
    int npad = tiles * 128;
    const int* src = eids;
    const int* dst = eids + E;

    cudaFuncSetAttribute((const void*)mma_gemm,
                         cudaFuncAttributeMaxDynamicSharedMemorySize, SMEM_SZ);

    float *p_delta, *p_q, *p_k, *p_v;
    __nv_bfloat16 *p_sh, *p_sl, *p_dh, *p_dl, *p_dsh, *p_dsl, *p_agh, *p_agl;
    int* p_hist;
    cudaGetSymbolAddress((void**)&p_delta, g_delta);
    cudaGetSymbolAddress((void**)&p_q, g_q);
    cudaGetSymbolAddress((void**)&p_k, g_k);
    cudaGetSymbolAddress((void**)&p_v, g_v);
    cudaGetSymbolAddress((void**)&p_sh, g_sh);
    cudaGetSymbolAddress((void**)&p_sl, g_sl);
    cudaGetSymbolAddress((void**)&p_dh, g_dh);
    cudaGetSymbolAddress((void**)&p_dl, g_dl);
    cudaGetSymbolAddress((void**)&p_dsh, g_dsh);
    cudaGetSymbolAddress((void**)&p_dsl, g_dsl);
    cudaGetSymbolAddress((void**)&p_agh, g_agh);
    cudaGetSymbolAddress((void**)&p_agl, g_agl);
    cudaGetSymbolAddress((void**)&p_hist, g_hist);

    // node-wise prep: LN+GELU, delta/struc hi-lo split (pads zeroed)
    ln_gelu_kernel<<<npad / 8, 256>>>(in_feats, struc, ln_s, ln_b, N, npad);
    // weight hi/lo split
    conv_w_kernel<<<5, 256>>>(Ws, Wq, Wk, Wv, Wo);

    // counting sort edges by src (independent of GEMMs)
    cudaMemsetAsync(p_hist, 0, N * sizeof(int));
    hist_kernel<<<(E + 255) / 256, 256>>>(src, E);
    scan_kernel<<<1, 1024>>>(N);
    scatter_kernel<<<(E + 255) / 256, 256>>>(src, dst, ew, E);

    // ds = delta + struc @ Ws^T + bs  (hi/lo only)
    mma_gemm<<<tiles, 256, SMEM_SZ>>>(p_sh, p_sl, 0, bs, p_delta, nullptr, p_dsh, p_dsl, npad, 1.0f);
    // q = (ds @ Wq^T + bq) / 4
    mma_gemm<<<tiles, 256, SMEM_SZ>>>(p_dsh, p_dsl, 1, bq, nullptr, p_q, nullptr, nullptr, N, 0.25f);
    // k = ds @ Wk^T + bk
    mma_gemm<<<tiles, 256, SMEM_SZ>>>(p_dsh, p_dsl, 2, bk, nullptr, p_k, nullptr, nullptr, N, 1.0f);
    // v = delta @ Wv^T + bv
    mma_gemm<<<tiles, 256, SMEM_SZ>>>(p_dh, p_dl, 3, bv, nullptr, p_v, nullptr, nullptr, N, 1.0f);

    // per-node sigmoid attention aggregation -> agg hi/lo
    agg_kernel<<<(N * 32 + 255) / 256, 256>>>(N);

    // out = agg @ Wo^T + in_feats
    mma_gemm<<<tiles, 256, SMEM_SZ>>>(p_agh, p_agl, 4, nullptr, in_feats, (float*)d_out, nullptr, nullptr, N, 1.0f);
}